// round 14
// baseline (speedup 1.0000x reference)
#include <cuda_runtime.h>
#include <cuda_bf16.h>

// Problem constants
#define BB 8
#define CC 64
#define HP 32
#define WP 32
#define NN 1024          // HP*WP
#define NHEADS 16
// scale * log2(e) = 0.5 * 1.4426950408889634
#define ALPHA 0.72134752044448169f

// Scratch (no cudaMalloc allowed)
__device__ float  g_t[BB * CC * NN];           // pooled activations [b][c][n]
__device__ float4 g_q4[BB * NHEADS * NN];      // [b][h][n][4], q pre-scaled by ALPHA
__device__ float4 g_k4[BB * NHEADS * NN];
__device__ float4 g_v4[BB * NHEADS * NN];
__device__ float  g_ot[BB * CC * NN];          // attention out TRANSPOSED [b][j=h*4+d][n]
__device__ unsigned char g_idx[BB * CC * NN];  // argmax within 2x2 window

typedef unsigned long long ull;

// ---- packed fp32 (f32x2) helpers ----
__device__ __forceinline__ ull pack2(float a, float b) {
    ull r;
    asm("mov.b64 %0, {%1,%2};" : "=l"(r) : "f"(a), "f"(b));
    return r;
}
__device__ __forceinline__ void unpack2(ull p, float& a, float& b) {
    asm("mov.b64 {%0,%1}, %2;" : "=f"(a), "=f"(b) : "l"(p));
}
__device__ __forceinline__ ull mul2(ull a, ull b) {
    ull r;
    asm("mul.rn.f32x2 %0, %1, %2;" : "=l"(r) : "l"(a), "l"(b));
    return r;
}
__device__ __forceinline__ ull add2(ull a, ull b) {
    ull r;
    asm("add.rn.f32x2 %0, %1, %2;" : "=l"(r) : "l"(a), "l"(b));
    return r;
}
__device__ __forceinline__ ull fma2(ull a, ull b, ull c) {
    ull r;
    asm("fma.rn.f32x2 %0, %1, %2, %3;" : "=l"(r) : "l"(a), "l"(b), "l"(c));
    return r;
}
__device__ __forceinline__ float ex2f(float x) {
    float r;
    asm("ex2.approx.f32 %0, %1;" : "=f"(r) : "f"(x));
    return r;
}

// ---------------------------------------------------------------------------
// Kernel A0: 2x2 maxpool + argmax -> g_t, g_idx. Memory-bound (~8MB read).
// grid 256 = (b, hp), 256 threads.
// ---------------------------------------------------------------------------
__global__ __launch_bounds__(256) void kA0(const float* __restrict__ x) {
    const int tid = threadIdx.x;
    const int blk = blockIdx.x;
    const int b = blk >> 5, hp = blk & 31;
#pragma unroll
    for (int s = 0; s < 8; s++) {
        int p = tid + s * 256;
        int c = p >> 5, wp = p & 31;
        const float* base = x + (((b * 64 + c) * 64 + 2 * hp) * 64 + 2 * wp);
        float2 a  = *(const float2*)(base);
        float2 d2 = *(const float2*)(base + 64);
        float best = a.x; int bi = 0;
        if (a.y  > best) { best = a.y;  bi = 1; }
        if (d2.x > best) { best = d2.x; bi = 2; }
        if (d2.y > best) { best = d2.y; bi = 3; }
        int n = hp * 32 + wp;
        g_t[(b * 64 + c) * 1024 + n] = best;
        g_idx[(b * 64 + c) * 1024 + n] = (unsigned char)bi;
    }
}

// ---------------------------------------------------------------------------
// Kernel A1: qkv = t @ w_qkv (64 x 192). grid 768 = b(8) x nch(16) x colg(6),
// 128 threads. Block = 64 n x 32 cols; thread = 4 n x 4 cols (8 packed acc).
// ---------------------------------------------------------------------------
__global__ __launch_bounds__(128) void kA1(const float* __restrict__ wq) {
    __shared__ float wsm[64 * 32];    // [c][j], 8KB
    __shared__ float4 tsm4[64 * 16];  // [c][n-quad], 16KB
    const int tid = threadIdx.x;
    const int blk = blockIdx.x;
    const int colg = blk % 6;
    const int nch = (blk / 6) & 15;
    const int b = blk / 96;

    // Stage weights: 64 rows x 32 cols = 512 float4.
#pragma unroll
    for (int s = 0; s < 4; s++) {
        int idx = tid + s * 128;
        int c = idx >> 3, j4 = idx & 7;
        *(float4*)&wsm[c * 32 + j4 * 4] =
            *(const float4*)(wq + c * 192 + colg * 32 + j4 * 4);
    }
    // Stage t slice: 64 c x 64 n = 1024 float4.
#pragma unroll
    for (int s = 0; s < 8; s++) {
        int idx = tid + s * 128;
        int c = idx >> 4, n4 = idx & 15;
        tsm4[c * 16 + n4] =
            *(const float4*)(g_t + (b * 64 + c) * 1024 + nch * 64 + n4 * 4);
    }
    __syncthreads();

    const int ng = tid >> 3;   // 16 n-quads
    const int cg = tid & 7;    // 8 col-quads
    ull acc[8];
#pragma unroll
    for (int j = 0; j < 8; j++) acc[j] = 0ull;

#pragma unroll 4
    for (int c = 0; c < 64; c++) {
        float4 t4 = tsm4[c * 16 + ng];
        ulonglong2 w = *(const ulonglong2*)&wsm[c * 32 + cg * 4];
        ull tp0 = pack2(t4.x, t4.x), tp1 = pack2(t4.y, t4.y);
        ull tp2 = pack2(t4.z, t4.z), tp3 = pack2(t4.w, t4.w);
        acc[0] = fma2(tp0, w.x, acc[0]);
        acc[1] = fma2(tp0, w.y, acc[1]);
        acc[2] = fma2(tp1, w.x, acc[2]);
        acc[3] = fma2(tp1, w.y, acc[3]);
        acc[4] = fma2(tp2, w.x, acc[4]);
        acc[5] = fma2(tp2, w.y, acc[5]);
        acc[6] = fma2(tp3, w.x, acc[6]);
        acc[7] = fma2(tp3, w.y, acc[7]);
    }

    // Epilogue: 4 cols = exactly one head's 4 dims -> 4 float4 stores.
    const int col = colg * 32 + cg * 4;
    const int sp = col >> 6;
    const int hh = (col & 63) >> 2;
#pragma unroll
    for (int nl = 0; nl < 4; nl++) {
        float a0, a1, a2, a3;
        unpack2(acc[nl * 2], a0, a1);
        unpack2(acc[nl * 2 + 1], a2, a3);
        int n = nch * 64 + ng * 4 + nl;
        int off = (b * 16 + hh) * 1024 + n;
        if (sp == 0) {
            g_q4[off] = make_float4(a0 * ALPHA, a1 * ALPHA, a2 * ALPHA, a3 * ALPHA);
        } else if (sp == 1) {
            g_k4[off] = make_float4(a0, a1, a2, a3);
        } else {
            g_v4[off] = make_float4(a0, a1, a2, a3);
        }
    }
}

// ---------------------------------------------------------------------------
// Kernel B: attention. grid 512 = (b,h) x 4 query-chunks of 256, 128 threads,
// 2 queries per thread (amortizes K/V LDS over 2 dots). All lanes read the
// SAME smem entry per iter (broadcast, conflict-free). Max-free exp2 softmax,
// packed fma.rn.f32x2 over m-pairs. Fine-grained blocks smooth the wave
// quantization that cost 15.6% at grid 256. Writes o TRANSPOSED for kC.
// ---------------------------------------------------------------------------
__global__ __launch_bounds__(128) void kB() {
    __shared__ float4 ksmA[512], ksmB[512];
    __shared__ float4 vsmA[512], vsmB[512];
    const int tid = threadIdx.x;
    const int blk = blockIdx.x;
    const int bh = blk >> 2;          // b*16 + h
    const int qc = blk & 3;           // query chunk of 256

    const float4* kg = g_k4 + bh * 1024;
    const float4* vg = g_v4 + bh * 1024;
#pragma unroll
    for (int s = 0; s < 4; s++) {
        int e = tid + s * 128;
        float4 k0 = kg[2 * e], k1 = kg[2 * e + 1];
        ksmA[e] = make_float4(k0.x, k1.x, k0.y, k1.y);
        ksmB[e] = make_float4(k0.z, k1.z, k0.w, k1.w);
        float4 v0 = vg[2 * e], v1 = vg[2 * e + 1];
        vsmA[e] = make_float4(v0.x, v1.x, v0.y, v1.y);
        vsmB[e] = make_float4(v0.z, v1.z, v0.w, v1.w);
    }

    const int nq0 = qc * 256 + tid;
    const int nq1 = nq0 + 128;
    float4 q0 = ((const float4*)g_q4)[bh * 1024 + nq0];
    float4 q1 = ((const float4*)g_q4)[bh * 1024 + nq1];
    ull q0x = pack2(q0.x, q0.x), q0y = pack2(q0.y, q0.y);
    ull q0z = pack2(q0.z, q0.z), q0w = pack2(q0.w, q0.w);
    ull q1x = pack2(q1.x, q1.x), q1y = pack2(q1.y, q1.y);
    ull q1z = pack2(q1.z, q1.z), q1w = pack2(q1.w, q1.w);
    __syncthreads();

    ull s0 = 0ull, ax0 = 0ull, ay0 = 0ull, az0 = 0ull, aw0 = 0ull;
    ull s1 = 0ull, ax1 = 0ull, ay1 = 0ull, az1 = 0ull, aw1 = 0ull;

#pragma unroll 4
    for (int mp = 0; mp < 512; mp++) {
        ulonglong2 ka = *(const ulonglong2*)&ksmA[mp];  // kx pair, ky pair
        ulonglong2 kb = *(const ulonglong2*)&ksmB[mp];  // kz pair, kw pair

        ull d0 = mul2(q0x, ka.x);
        d0 = fma2(q0y, ka.y, d0);
        d0 = fma2(q0z, kb.x, d0);
        d0 = fma2(q0w, kb.y, d0);
        ull d1 = mul2(q1x, ka.x);
        d1 = fma2(q1y, ka.y, d1);
        d1 = fma2(q1z, kb.x, d1);
        d1 = fma2(q1w, kb.y, d1);

        float d0e, d0o, d1e, d1o;
        unpack2(d0, d0e, d0o);
        unpack2(d1, d1e, d1o);
        ull e0 = pack2(ex2f(d0e), ex2f(d0o));
        ull e1 = pack2(ex2f(d1e), ex2f(d1o));

        ulonglong2 va = *(const ulonglong2*)&vsmA[mp];
        ulonglong2 vb = *(const ulonglong2*)&vsmB[mp];

        s0  = add2(s0, e0);
        ax0 = fma2(e0, va.x, ax0);
        ay0 = fma2(e0, va.y, ay0);
        az0 = fma2(e0, vb.x, az0);
        aw0 = fma2(e0, vb.y, aw0);
        s1  = add2(s1, e1);
        ax1 = fma2(e1, va.x, ax1);
        ay1 = fma2(e1, va.y, ay1);
        az1 = fma2(e1, vb.x, az1);
        aw1 = fma2(e1, vb.y, aw1);
    }

    const int b = bh >> 4, h = bh & 15;
    const int obase = (b * 64 + h * 4) * 1024;   // [b][j=h*4+d][n]
    float se, so, xe, xo, ye, yo, ze, zo, we, wo;

    unpack2(s0, se, so);
    float r0 = 1.0f / (se + so);
    unpack2(ax0, xe, xo); unpack2(ay0, ye, yo);
    unpack2(az0, ze, zo); unpack2(aw0, we, wo);
    g_ot[obase + nq0]        = (xe + xo) * r0;
    g_ot[obase + 1024 + nq0] = (ye + yo) * r0;
    g_ot[obase + 2048 + nq0] = (ze + zo) * r0;
    g_ot[obase + 3072 + nq0] = (we + wo) * r0;

    unpack2(s1, se, so);
    float r1 = 1.0f / (se + so);
    unpack2(ax1, xe, xo); unpack2(ay1, ye, yo);
    unpack2(az1, ze, zo); unpack2(aw1, we, wo);
    g_ot[obase + nq1]        = (xe + xo) * r1;
    g_ot[obase + 1024 + nq1] = (ye + yo) * r1;
    g_ot[obase + 2048 + nq1] = (ze + zo) * r1;
    g_ot[obase + 3072 + nq1] = (we + wo) * r1;
}

// ---------------------------------------------------------------------------
// Kernel C: o @ w_proj (64x64) + BN affine + argmax unpool scatter.
// grid 128 = (b, nch of 64 n), 128 threads; thread = 4 n x 8 cols from the
// TRANSPOSED o (3 LDS.128 per 32 FMAs), affine + scatter straight from regs.
// Replaces the R13 version that measured 18.0us (latency/occupancy-bound).
// ---------------------------------------------------------------------------
__global__ __launch_bounds__(128) void kC(const float* __restrict__ wproj,
                                          const float* __restrict__ gamma,
                                          const float* __restrict__ beta,
                                          const float* __restrict__ bmean,
                                          const float* __restrict__ bvar,
                                          float* __restrict__ out) {
    __shared__ float wsm[64 * 64];    // 16KB
    __shared__ float4 osm4[64 * 16];  // [c][n-quad], 16KB
    __shared__ float invs[64], adds[64];

    const int tid = threadIdx.x;
    const int blk = blockIdx.x;
    const int b = blk >> 4, nch = blk & 15;

    // Stage w_proj: 1024 float4, coalesced.
#pragma unroll
    for (int s = 0; s < 8; s++) {
        int idx = tid + s * 128;
        *(float4*)&wsm[idx * 4] = *(const float4*)(wproj + idx * 4);
    }
    // Stage transposed o slice: 64 c x 16 n-quads, coalesced.
#pragma unroll
    for (int s = 0; s < 8; s++) {
        int idx = tid + s * 128;
        int c = idx >> 4, nq = idx & 15;
        osm4[c * 16 + nq] =
            *(const float4*)(g_ot + (b * 64 + c) * 1024 + nch * 64 + nq * 4);
    }
    if (tid < 64) {
        float inv = gamma[tid] * rsqrtf(bvar[tid] + 1e-5f);
        invs[tid] = inv;
        adds[tid] = fmaf(-bmean[tid], inv, beta[tid]);
    }
    __syncthreads();

    const int ng = tid >> 3;   // 16 n-quads
    const int cg = tid & 7;    // 8 col-groups of 8
    ull acc[16];               // acc[nl*4 + jp] = cols (cg*8+2jp, +1) for row nl
#pragma unroll
    for (int j = 0; j < 16; j++) acc[j] = 0ull;

#pragma unroll 4
    for (int c = 0; c < 64; c++) {
        float4 o4 = osm4[c * 16 + ng];
        const ulonglong2* wrow = (const ulonglong2*)&wsm[c * 64 + cg * 8];
        ulonglong2 w0 = wrow[0], w1 = wrow[1];
        ull tp0 = pack2(o4.x, o4.x), tp1 = pack2(o4.y, o4.y);
        ull tp2 = pack2(o4.z, o4.z), tp3 = pack2(o4.w, o4.w);
        acc[0]  = fma2(tp0, w0.x, acc[0]);
        acc[1]  = fma2(tp0, w0.y, acc[1]);
        acc[2]  = fma2(tp0, w1.x, acc[2]);
        acc[3]  = fma2(tp0, w1.y, acc[3]);
        acc[4]  = fma2(tp1, w0.x, acc[4]);
        acc[5]  = fma2(tp1, w0.y, acc[5]);
        acc[6]  = fma2(tp1, w1.x, acc[6]);
        acc[7]  = fma2(tp1, w1.y, acc[7]);
        acc[8]  = fma2(tp2, w0.x, acc[8]);
        acc[9]  = fma2(tp2, w0.y, acc[9]);
        acc[10] = fma2(tp2, w1.x, acc[10]);
        acc[11] = fma2(tp2, w1.y, acc[11]);
        acc[12] = fma2(tp3, w0.x, acc[12]);
        acc[13] = fma2(tp3, w0.y, acc[13]);
        acc[14] = fma2(tp3, w1.x, acc[14]);
        acc[15] = fma2(tp3, w1.y, acc[15]);
    }

    // Affine into v[n][col], then scatter (idx via uchar4 per col).
    float v[4][8];
#pragma unroll
    for (int nl = 0; nl < 4; nl++) {
#pragma unroll
        for (int jp = 0; jp < 4; jp++) {
            float a0, a1;
            unpack2(acc[nl * 4 + jp], a0, a1);
            int c0 = cg * 8 + jp * 2;
            v[nl][jp * 2]     = fmaf(a0, invs[c0], adds[c0]);
            v[nl][jp * 2 + 1] = fmaf(a1, invs[c0 + 1], adds[c0 + 1]);
        }
    }

    const int nbase = nch * 64 + ng * 4;        // 4-aligned, same hp for quad
    const int hp = nbase >> 5, wp0 = nbase & 31;
#pragma unroll
    for (int j = 0; j < 8; j++) {
        int c = cg * 8 + j;
        uchar4 k4 = *(const uchar4*)(g_idx + (b * 64 + c) * 1024 + nbase);
        float* obase = out + (((b * 64 + c) * 64 + 2 * hp) * 64);
        unsigned char ks[4] = {k4.x, k4.y, k4.z, k4.w};
#pragma unroll
        for (int nl = 0; nl < 4; nl++) {
            float val = v[nl][j];
            unsigned char kk = ks[nl];
            float2 top = make_float2(kk == 0 ? val : 0.f, kk == 1 ? val : 0.f);
            float2 bot = make_float2(kk == 2 ? val : 0.f, kk == 3 ? val : 0.f);
            float* ob = obase + 2 * (wp0 + nl);
            *(float2*)(ob)      = top;
            *(float2*)(ob + 64) = bot;
        }
    }
}

// ---------------------------------------------------------------------------
extern "C" void kernel_launch(void* const* d_in, const int* in_sizes, int n_in,
                              void* d_out, int out_size) {
    const float* x      = (const float*)d_in[0];
    const float* w_qkv  = (const float*)d_in[1];
    const float* w_proj = (const float*)d_in[2];
    const float* gamma  = (const float*)d_in[3];
    const float* beta   = (const float*)d_in[4];
    const float* bmean  = (const float*)d_in[5];
    const float* bvar   = (const float*)d_in[6];
    float* out = (float*)d_out;

    kA0<<<256, 256>>>(x);
    kA1<<<768, 128>>>(w_qkv);
    kB<<<512, 128>>>();
    kC<<<128, 128>>>(w_proj, gamma, beta, bmean, bvar, out);
}

// round 17
// speedup vs baseline: 1.0625x; 1.0625x over previous
#include <cuda_runtime.h>
#include <cuda_bf16.h>

// Problem constants
#define BB 8
#define CC 64
#define HP 32
#define WP 32
#define NN 1024          // HP*WP
#define NHEADS 16
// scale * log2(e) = 0.5 * 1.4426950408889634
#define ALPHA 0.72134752044448169f

// Scratch (no cudaMalloc allowed)
__device__ float  g_t[BB * CC * NN];           // pooled activations [b][c][n]
__device__ float4 g_q4[BB * NHEADS * NN];      // [b][h][n][4], q pre-scaled by ALPHA
__device__ float4 g_k4[BB * NHEADS * NN];
__device__ float4 g_v4[BB * NHEADS * NN];
__device__ float4 g_p0[BB * NHEADS * NN];      // partial o-accum, m-half 0  [bh][n]
__device__ float4 g_p1[BB * NHEADS * NN];      // partial o-accum, m-half 1
__device__ float  g_s0[BB * NHEADS * NN];      // partial exp-sum, m-half 0
__device__ float  g_s1[BB * NHEADS * NN];      // partial exp-sum, m-half 1
__device__ unsigned char g_idx[BB * CC * NN];  // argmax within 2x2 window

typedef unsigned long long ull;

// ---- packed fp32 (f32x2) helpers ----
__device__ __forceinline__ ull pack2(float a, float b) {
    ull r;
    asm("mov.b64 %0, {%1,%2};" : "=l"(r) : "f"(a), "f"(b));
    return r;
}
__device__ __forceinline__ void unpack2(ull p, float& a, float& b) {
    asm("mov.b64 {%0,%1}, %2;" : "=f"(a), "=f"(b) : "l"(p));
}
__device__ __forceinline__ ull mul2(ull a, ull b) {
    ull r;
    asm("mul.rn.f32x2 %0, %1, %2;" : "=l"(r) : "l"(a), "l"(b));
    return r;
}
__device__ __forceinline__ ull add2(ull a, ull b) {
    ull r;
    asm("add.rn.f32x2 %0, %1, %2;" : "=l"(r) : "l"(a), "l"(b));
    return r;
}
__device__ __forceinline__ ull fma2(ull a, ull b, ull c) {
    ull r;
    asm("fma.rn.f32x2 %0, %1, %2, %3;" : "=l"(r) : "l"(a), "l"(b), "l"(c));
    return r;
}
__device__ __forceinline__ float ex2f(float x) {
    float r;
    asm("ex2.approx.f32 %0, %1;" : "=f"(r) : "f"(x));
    return r;
}

// ---------------------------------------------------------------------------
// Kernel A0: 2x2 maxpool + argmax -> g_t, g_idx. Memory-bound (~8MB read).
// grid 256 = (b, hp), 256 threads.
// ---------------------------------------------------------------------------
__global__ __launch_bounds__(256) void kA0(const float* __restrict__ x) {
    const int tid = threadIdx.x;
    const int blk = blockIdx.x;
    const int b = blk >> 5, hp = blk & 31;
#pragma unroll
    for (int s = 0; s < 8; s++) {
        int p = tid + s * 256;
        int c = p >> 5, wp = p & 31;
        const float* base = x + (((b * 64 + c) * 64 + 2 * hp) * 64 + 2 * wp);
        float2 a  = *(const float2*)(base);
        float2 d2 = *(const float2*)(base + 64);
        float best = a.x; int bi = 0;
        if (a.y  > best) { best = a.y;  bi = 1; }
        if (d2.x > best) { best = d2.x; bi = 2; }
        if (d2.y > best) { best = d2.y; bi = 3; }
        int n = hp * 32 + wp;
        g_t[(b * 64 + c) * 1024 + n] = best;
        g_idx[(b * 64 + c) * 1024 + n] = (unsigned char)bi;
    }
}

// ---------------------------------------------------------------------------
// Kernel A1: qkv = t @ w_qkv (64 x 192). grid 768 = b(8) x nch(16) x colg(6),
// 128 threads. Block = 64 n x 32 cols; thread = 4 n x 4 cols (8 packed acc).
// ---------------------------------------------------------------------------
__global__ __launch_bounds__(128) void kA1(const float* __restrict__ wq) {
    __shared__ float wsm[64 * 32];    // [c][j], 8KB
    __shared__ float4 tsm4[64 * 16];  // [c][n-quad], 16KB
    const int tid = threadIdx.x;
    const int blk = blockIdx.x;
    const int colg = blk % 6;
    const int nch = (blk / 6) & 15;
    const int b = blk / 96;

    // Stage weights: 64 rows x 32 cols = 512 float4.
#pragma unroll
    for (int s = 0; s < 4; s++) {
        int idx = tid + s * 128;
        int c = idx >> 3, j4 = idx & 7;
        *(float4*)&wsm[c * 32 + j4 * 4] =
            *(const float4*)(wq + c * 192 + colg * 32 + j4 * 4);
    }
    // Stage t slice: 64 c x 64 n = 1024 float4.
#pragma unroll
    for (int s = 0; s < 8; s++) {
        int idx = tid + s * 128;
        int c = idx >> 4, n4 = idx & 15;
        tsm4[c * 16 + n4] =
            *(const float4*)(g_t + (b * 64 + c) * 1024 + nch * 64 + n4 * 4);
    }
    __syncthreads();

    const int ng = tid >> 3;   // 16 n-quads
    const int cg = tid & 7;    // 8 col-quads
    ull acc[8];
#pragma unroll
    for (int j = 0; j < 8; j++) acc[j] = 0ull;

#pragma unroll 4
    for (int c = 0; c < 64; c++) {
        float4 t4 = tsm4[c * 16 + ng];
        ulonglong2 w = *(const ulonglong2*)&wsm[c * 32 + cg * 4];
        ull tp0 = pack2(t4.x, t4.x), tp1 = pack2(t4.y, t4.y);
        ull tp2 = pack2(t4.z, t4.z), tp3 = pack2(t4.w, t4.w);
        acc[0] = fma2(tp0, w.x, acc[0]);
        acc[1] = fma2(tp0, w.y, acc[1]);
        acc[2] = fma2(tp1, w.x, acc[2]);
        acc[3] = fma2(tp1, w.y, acc[3]);
        acc[4] = fma2(tp2, w.x, acc[4]);
        acc[5] = fma2(tp2, w.y, acc[5]);
        acc[6] = fma2(tp3, w.x, acc[6]);
        acc[7] = fma2(tp3, w.y, acc[7]);
    }

    // Epilogue: 4 cols = exactly one head's 4 dims -> 4 float4 stores.
    const int col = colg * 32 + cg * 4;
    const int sp = col >> 6;
    const int hh = (col & 63) >> 2;
#pragma unroll
    for (int nl = 0; nl < 4; nl++) {
        float a0, a1, a2, a3;
        unpack2(acc[nl * 2], a0, a1);
        unpack2(acc[nl * 2 + 1], a2, a3);
        int n = nch * 64 + ng * 4 + nl;
        int off = (b * 16 + hh) * 1024 + n;
        if (sp == 0) {
            g_q4[off] = make_float4(a0 * ALPHA, a1 * ALPHA, a2 * ALPHA, a3 * ALPHA);
        } else if (sp == 1) {
            g_k4[off] = make_float4(a0, a1, a2, a3);
        } else {
            g_v4[off] = make_float4(a0, a1, a2, a3);
        }
    }
}

// ---------------------------------------------------------------------------
// Kernel B: attention partials. grid 1024 = bh(128) x qchunk(4, 256 q) x
// mhalf(2, 512 keys), 128 threads, 2 queries/thread. Block loads ONLY its
// K/V half (16KB) -> ~14-block residency, 6.92 avg blocks/SM = single wave
// (kills the 15.6% tax of grid 256). Writes UNNORMALIZED partial (o, s);
// kC combines the two m-halves. Broadcast LDS (all lanes same entry),
// max-free exp2 softmax, packed fma.rn.f32x2 over m-pairs.
// ---------------------------------------------------------------------------
__global__ __launch_bounds__(128) void kB() {
    __shared__ float4 ksmA[256], ksmB[256];
    __shared__ float4 vsmA[256], vsmB[256];
    const int tid = threadIdx.x;
    const int blk = blockIdx.x;
    const int mh = blk & 1;           // m-half
    const int qc = (blk >> 1) & 3;    // query chunk of 256
    const int bh = blk >> 3;          // b*16 + h

    // Fill this block's 512-key half, m-pair-interleaved.
    const float4* kg = g_k4 + bh * 1024 + mh * 512;
    const float4* vg = g_v4 + bh * 1024 + mh * 512;
#pragma unroll
    for (int s = 0; s < 2; s++) {
        int e = tid + s * 128;        // local pair index [0,256)
        float4 k0 = kg[2 * e], k1 = kg[2 * e + 1];
        ksmA[e] = make_float4(k0.x, k1.x, k0.y, k1.y);
        ksmB[e] = make_float4(k0.z, k1.z, k0.w, k1.w);
        float4 v0 = vg[2 * e], v1 = vg[2 * e + 1];
        vsmA[e] = make_float4(v0.x, v1.x, v0.y, v1.y);
        vsmB[e] = make_float4(v0.z, v1.z, v0.w, v1.w);
    }

    const int nq0 = qc * 256 + tid;
    const int nq1 = nq0 + 128;
    float4 q0 = ((const float4*)g_q4)[bh * 1024 + nq0];
    float4 q1 = ((const float4*)g_q4)[bh * 1024 + nq1];
    ull q0x = pack2(q0.x, q0.x), q0y = pack2(q0.y, q0.y);
    ull q0z = pack2(q0.z, q0.z), q0w = pack2(q0.w, q0.w);
    ull q1x = pack2(q1.x, q1.x), q1y = pack2(q1.y, q1.y);
    ull q1z = pack2(q1.z, q1.z), q1w = pack2(q1.w, q1.w);
    __syncthreads();

    ull s0 = 0ull, ax0 = 0ull, ay0 = 0ull, az0 = 0ull, aw0 = 0ull;
    ull s1 = 0ull, ax1 = 0ull, ay1 = 0ull, az1 = 0ull, aw1 = 0ull;

#pragma unroll 4
    for (int mp = 0; mp < 256; mp++) {
        ulonglong2 ka = *(const ulonglong2*)&ksmA[mp];  // kx pair, ky pair
        ulonglong2 kb = *(const ulonglong2*)&ksmB[mp];  // kz pair, kw pair

        ull d0 = mul2(q0x, ka.x);
        d0 = fma2(q0y, ka.y, d0);
        d0 = fma2(q0z, kb.x, d0);
        d0 = fma2(q0w, kb.y, d0);
        ull d1 = mul2(q1x, ka.x);
        d1 = fma2(q1y, ka.y, d1);
        d1 = fma2(q1z, kb.x, d1);
        d1 = fma2(q1w, kb.y, d1);

        float d0e, d0o, d1e, d1o;
        unpack2(d0, d0e, d0o);
        unpack2(d1, d1e, d1o);
        ull e0 = pack2(ex2f(d0e), ex2f(d0o));
        ull e1 = pack2(ex2f(d1e), ex2f(d1o));

        ulonglong2 va = *(const ulonglong2*)&vsmA[mp];
        ulonglong2 vb = *(const ulonglong2*)&vsmB[mp];

        s0  = add2(s0, e0);
        ax0 = fma2(e0, va.x, ax0);
        ay0 = fma2(e0, va.y, ay0);
        az0 = fma2(e0, vb.x, az0);
        aw0 = fma2(e0, vb.y, aw0);
        s1  = add2(s1, e1);
        ax1 = fma2(e1, va.x, ax1);
        ay1 = fma2(e1, va.y, ay1);
        az1 = fma2(e1, vb.x, az1);
        aw1 = fma2(e1, vb.y, aw1);
    }

    // Store UNNORMALIZED partials (coalesced: consecutive tid -> consecutive n).
    float4* pp = mh ? g_p1 : g_p0;
    float*  sp = mh ? g_s1 : g_s0;
    float se0, so0, se1, so1, xe, xo, ye, yo, ze, zo, we, wo;

    unpack2(s0, se0, so0);
    unpack2(s1, se1, so1);
    sp[bh * 1024 + nq0] = se0 + so0;
    sp[bh * 1024 + nq1] = se1 + so1;

    unpack2(ax0, xe, xo); unpack2(ay0, ye, yo);
    unpack2(az0, ze, zo); unpack2(aw0, we, wo);
    pp[bh * 1024 + nq0] = make_float4(xe + xo, ye + yo, ze + zo, we + wo);

    unpack2(ax1, xe, xo); unpack2(ay1, ye, yo);
    unpack2(az1, ze, zo); unpack2(aw1, we, wo);
    pp[bh * 1024 + nq1] = make_float4(xe + xo, ye + yo, ze + zo, we + wo);
}

// ---------------------------------------------------------------------------
// Kernel C: combine attention partials + o @ w_proj (64x64) + BN affine +
// argmax unpool scatter. grid 256 = (b, hp), 256 threads, register-tiled
// 8 outputs/thread (R12-proven structure; staging now also normalizes).
// ---------------------------------------------------------------------------
__global__ __launch_bounds__(256) void kC(const float* __restrict__ wproj,
                                          const float* __restrict__ gamma,
                                          const float* __restrict__ beta,
                                          const float* __restrict__ bmean,
                                          const float* __restrict__ bvar,
                                          float* __restrict__ out) {
    __shared__ float wsm[64 * 64];   // 16KB
    __shared__ float osm[32 * 65];   // [nl][c], 65-stride = conflict-free
    __shared__ float psm[32 * 65];   // [nl][j]
    __shared__ float invs[64], adds[64];

    const int tid = threadIdx.x;
    const int blk = blockIdx.x;
    const int b = blk >> 5, hp = blk & 31;

#pragma unroll
    for (int s = 0; s < 16; s++) wsm[tid + s * 256] = wproj[tid + s * 256];

    // Stage o: combine m-half partials and normalize. i -> (h, nl).
#pragma unroll
    for (int s = 0; s < 2; s++) {
        int i = tid + s * 256;        // [0,512)
        int h = i >> 5, nl = i & 31;
        int gi = (b * 16 + h) * 1024 + hp * 32 + nl;
        float sv = g_s0[gi] + g_s1[gi];
        float r = 1.0f / sv;
        float4 p0 = g_p0[gi], p1 = g_p1[gi];
        osm[nl * 65 + h * 4 + 0] = (p0.x + p1.x) * r;
        osm[nl * 65 + h * 4 + 1] = (p0.y + p1.y) * r;
        osm[nl * 65 + h * 4 + 2] = (p0.z + p1.z) * r;
        osm[nl * 65 + h * 4 + 3] = (p0.w + p1.w) * r;
    }
    if (tid < 64) {
        float inv = gamma[tid] * rsqrtf(bvar[tid] + 1e-5f);
        invs[tid] = inv;
        adds[tid] = fmaf(-bmean[tid], inv, beta[tid]);
    }
    __syncthreads();

    // proj + affine: thread = (nl, colg); 8 cols per thread in registers.
    {
        const int nl = tid >> 3;
        const int colg = tid & 7;
        float acc[8];
#pragma unroll
        for (int j = 0; j < 8; j++) acc[j] = 0.f;
#pragma unroll 4
        for (int c = 0; c < 64; c++) {
            float ov = osm[nl * 65 + c];
            const float4* wrow = (const float4*)&wsm[c * 64 + colg * 8];
            float4 w0 = wrow[0], w1 = wrow[1];
            acc[0] = fmaf(ov, w0.x, acc[0]);
            acc[1] = fmaf(ov, w0.y, acc[1]);
            acc[2] = fmaf(ov, w0.z, acc[2]);
            acc[3] = fmaf(ov, w0.w, acc[3]);
            acc[4] = fmaf(ov, w1.x, acc[4]);
            acc[5] = fmaf(ov, w1.y, acc[5]);
            acc[6] = fmaf(ov, w1.z, acc[6]);
            acc[7] = fmaf(ov, w1.w, acc[7]);
        }
#pragma unroll
        for (int j = 0; j < 8; j++) {
            int col = colg * 8 + j;
            psm[nl * 65 + col] = fmaf(acc[j], invs[col], adds[col]);
        }
    }
    __syncthreads();

    // scatter into 2x2 windows (zeros at non-argmax positions)
#pragma unroll
    for (int s = 0; s < 8; s++) {
        int p = tid + s * 256;
        int c = p >> 5, wpx = p & 31;
        float val = psm[wpx * 65 + c];
        unsigned char kk = g_idx[(b * 64 + c) * 1024 + hp * 32 + wpx];
        float2 top = make_float2(kk == 0 ? val : 0.f, kk == 1 ? val : 0.f);
        float2 bot = make_float2(kk == 2 ? val : 0.f, kk == 3 ? val : 0.f);
        float* ob = out + (((b * 64 + c) * 64 + 2 * hp) * 64 + 2 * wpx);
        *(float2*)(ob)      = top;
        *(float2*)(ob + 64) = bot;
    }
}

// ---------------------------------------------------------------------------
extern "C" void kernel_launch(void* const* d_in, const int* in_sizes, int n_in,
                              void* d_out, int out_size) {
    const float* x      = (const float*)d_in[0];
    const float* w_qkv  = (const float*)d_in[1];
    const float* w_proj = (const float*)d_in[2];
    const float* gamma  = (const float*)d_in[3];
    const float* beta   = (const float*)d_in[4];
    const float* bmean  = (const float*)d_in[5];
    const float* bvar   = (const float*)d_in[6];
    float* out = (float*)d_out;

    kA0<<<256, 256>>>(x);
    kA1<<<768, 128>>>(w_qkv);
    kB<<<1024, 128>>>();
    kC<<<256, 256>>>(w_proj, gamma, beta, bmean, bvar, out);
}